// round 1
// baseline (speedup 1.0000x reference)
#include <cuda_runtime.h>
#include <math_constants.h>

// RankingLoss: B=16384 rows, C=1000 classes.
// per row: label = argmax(target); x1 = logits[label];
//   pair = sum_{j=1..C-1} relu(logits[j] - x1 + |label-j|/(C-1))
//   neg  = relu(logits[0] - x1 + 1)
//   per_sample = (label==0) ? 0 : pair + neg
// out = mean(per_sample)

#define C_CLASSES 1000
#define C4 250            // C / 4
#define THREADS 256

__global__ void ranking_loss_kernel(const float* __restrict__ logits,
                                    const float* __restrict__ target,
                                    float* __restrict__ out,
                                    float inv_B) {
    const int row = blockIdx.x;
    const int t = threadIdx.x;

    const float4* tgt4 = reinterpret_cast<const float4*>(target + (size_t)row * C_CLASSES);
    const float4* lgt4 = reinterpret_cast<const float4*>(logits + (size_t)row * C_CLASSES);

    // Issue both loads up front; logits load latency overlaps the argmax reduction.
    float4 tv = make_float4(0.f, 0.f, 0.f, 0.f);
    float4 lv = make_float4(0.f, 0.f, 0.f, 0.f);
    if (t < C4) {
        tv = tgt4[t];
        lv = lgt4[t];
    }

    // ---- per-thread argmax over its 4 target values (first-index tiebreak) ----
    float m = -CUDART_INF_F;
    int   mi = 0x7fffffff;
    if (t < C4) {
        const int base = 4 * t;
        m = tv.x; mi = base;
        if (tv.y > m) { m = tv.y; mi = base + 1; }
        if (tv.z > m) { m = tv.z; mi = base + 2; }
        if (tv.w > m) { m = tv.w; mi = base + 3; }
    }

    // ---- warp argmax reduction ----
    #pragma unroll
    for (int off = 16; off > 0; off >>= 1) {
        float om = __shfl_down_sync(0xffffffffu, m, off);
        int   oi = __shfl_down_sync(0xffffffffu, mi, off);
        if (om > m || (om == m && oi < mi)) { m = om; mi = oi; }
    }

    __shared__ float s_max[8];
    __shared__ int   s_idx[8];
    __shared__ int   s_label;
    __shared__ float s_x1;

    const int warp = t >> 5;
    const int lane = t & 31;
    if (lane == 0) { s_max[warp] = m; s_idx[warp] = mi; }
    __syncthreads();

    if (warp == 0) {
        float wm = (lane < 8) ? s_max[lane] : -CUDART_INF_F;
        int   wi = (lane < 8) ? s_idx[lane] : 0x7fffffff;
        #pragma unroll
        for (int off = 4; off > 0; off >>= 1) {
            float om = __shfl_down_sync(0xffffffffu, wm, off);
            int   oi = __shfl_down_sync(0xffffffffu, wi, off);
            if (om > wm || (om == wm && oi < wi)) { wm = om; wi = oi; }
        }
        if (lane == 0) s_label = wi;
    }
    __syncthreads();

    const int label = s_label;

    // ---- x1: the thread holding logits[label] publishes it (already in registers) ----
    if (t == (label >> 2)) {
        const int k = label & 3;
        float x1 = (k == 0) ? lv.x : (k == 1) ? lv.y : (k == 2) ? lv.z : lv.w;
        s_x1 = x1;
    }
    __syncthreads();

    const float x1 = s_x1;
    const float inv_pos = 1.0f / (float)(C_CLASSES - 1);
    const float flabel = (float)label;

    // ---- per-thread margin-relu sum over its 4 logits ----
    float sum = 0.f;
    if (t < C4 && label != 0) {
        const int base = 4 * t;
        #pragma unroll
        for (int k = 0; k < 4; k++) {
            const int j = base + k;
            const float l = (k == 0) ? lv.x : (k == 1) ? lv.y : (k == 2) ? lv.z : lv.w;
            // j==0 -> neg term with margin 1.0 (NEG_MARGIN=1.0 multiplier)
            const float margin = (j == 0) ? 1.0f : fabsf(flabel - (float)j) * inv_pos;
            sum += fmaxf(0.f, l - x1 + margin);
        }
    }

    // ---- block sum reduction ----
    #pragma unroll
    for (int off = 16; off > 0; off >>= 1)
        sum += __shfl_down_sync(0xffffffffu, sum, off);

    __shared__ float s_sum[8];
    if (lane == 0) s_sum[warp] = sum;
    __syncthreads();

    if (warp == 0) {
        float v = (lane < 8) ? s_sum[lane] : 0.f;
        #pragma unroll
        for (int off = 4; off > 0; off >>= 1)
            v += __shfl_down_sync(0xffffffffu, v, off);
        if (lane == 0 && v != 0.f)
            atomicAdd(out, v * inv_B);
    }
}

extern "C" void kernel_launch(void* const* d_in, const int* in_sizes, int n_in,
                              void* d_out, int out_size) {
    const float* logits = (const float*)d_in[0];
    const float* target = (const float*)d_in[1];
    float* out = (float*)d_out;

    const int B = in_sizes[0] / C_CLASSES;  // 16384

    cudaMemsetAsync(out, 0, sizeof(float));
    ranking_loss_kernel<<<B, THREADS>>>(logits, target, out, 1.0f / (float)B);
}